// round 12
// baseline (speedup 1.0000x reference)
#include <cuda_runtime.h>
#include <math.h>

// Problem constants
#define BB   8
#define NIN  256
#define DD   128
#define KK   1024
#define NNN  4096
#define TN   128          // columns per CTA tile
#define NTH  256          // threads per CTA
#define KB   64           // codebook rows per chunk
#define CB   32           // input channels per chunk (GEMM1)
#define ZQ_SIZE (BB*DD*NNN)

typedef unsigned long long u64;

// Scratch (no cudaMalloc allowed)
__device__ float g_zsum[KK*DD];
__device__ float g_nsum[KK];
__device__ float g_qsq[KK];
__device__ float g_qsrt[KK];

// ---- packed f32x2 helpers (FFMA2: 2x fp32 FMA throughput on sm_103a) ----
__device__ __forceinline__ u64 bcast2(float a) {
    u64 r; unsigned u = __float_as_uint(a);
    asm("mov.b64 %0, {%1, %1};" : "=l"(r) : "r"(u));
    return r;
}
__device__ __forceinline__ void ffma2(u64 &d, u64 a, u64 b) {
    asm("fma.rn.f32x2 %0, %1, %2, %0;" : "+l"(d) : "l"(a), "l"(b));
}

// ============================================================
// Kernel 1: zero scatter accumulators, precompute ||emb_k||^2 and sqrt
// grid = KK blocks of 128 threads (one block per codebook row)
// ============================================================
__global__ void vq_init(const float* __restrict__ emb) {
    const int k = blockIdx.x;
    const int t = threadIdx.x;
    const float v = emb[k * DD + t];
    g_zsum[k * DD + t] = 0.0f;
    float s = v * v;
    #pragma unroll
    for (int o = 16; o > 0; o >>= 1) s += __shfl_xor_sync(0xffffffffu, s, o);
    __shared__ float red[4];
    if ((t & 31) == 0) red[t >> 5] = s;
    __syncthreads();
    if (t == 0) {
        const float tot = (red[0] + red[1]) + (red[2] + red[3]);
        g_nsum[k] = 0.0f;
        g_qsq[k]  = tot;
        g_qsrt[k] = sqrtf(tot);
    }
}

// ============================================================
// Kernel 2: fused  ze-GEMM -> distance GEMM -> argmin -> zq gather
//           -> EMA scatter-add.   grid = BB * (NNN/TN) = 256 CTAs.
// ============================================================
__global__ void __launch_bounds__(NTH)
vq_main(const float* __restrict__ z, const float* __restrict__ W,
        const float* __restrict__ emb, float* __restrict__ out)
{
    extern __shared__ float smem[];
    float* ze_s = smem;            // [128 d][128 j]  = 16384 floats (64KB)
    float* buf  = smem + DD * TN;  // 8256-float union region (33KB)

    __shared__ float zsq_s[TN];
    __shared__ float zsrt_s[TN];
    __shared__ float qsq_s[KB];
    __shared__ float qsrt_s[KB];
    __shared__ int   bestk_s[TN];

    const int tid = threadIdx.x;
    const int b   = blockIdx.x >> 5;          // batch
    const int n0  = (blockIdx.x & 31) * TN;   // column tile origin
    const int rg  = tid & 15;                 // row group (d or k)
    const int jg  = tid >> 4;                 // column group (8 cols each)

    // ---------------- Phase 1: ze[d][j] = sum_c W[d][c] * z[b][c][n0+j]
    // register tile: 8 d-rows x 8 j-cols (4 f32x2 pairs) per thread
    {
        float* w_s  = buf;          // [CB][129]  (pad to kill write conflicts)
        float* zc_s = buf + 4160;   // [CB][128]
        u64 acc[8][4];
        #pragma unroll
        for (int i = 0; i < 8; i++)
            #pragma unroll
            for (int p = 0; p < 4; p++) acc[i][p] = 0ull;

        for (int cc = 0; cc < NIN; cc += CB) {
            __syncthreads();
            #pragma unroll
            for (int it = 0; it < (DD * CB) / NTH; it++) {     // 16
                const int i = tid + it * NTH;
                const int d = i >> 5, cl = i & 31;
                w_s[cl * 129 + d] = W[d * NIN + cc + cl];
            }
            #pragma unroll
            for (int it = 0; it < (CB * TN) / NTH; it++) {     // 16
                const int i = tid + it * NTH;
                const int cl = i >> 7, j = i & 127;
                zc_s[cl * 128 + j] = z[((size_t)b * NIN + cc + cl) * NNN + n0 + j];
            }
            __syncthreads();
            #pragma unroll 2
            for (int cl = 0; cl < CB; cl++) {
                u64 bfrag[4];
                const u64* bp = (const u64*)(zc_s + cl * 128 + jg * 8);
                #pragma unroll
                for (int p = 0; p < 4; p++) bfrag[p] = bp[p];
                #pragma unroll
                for (int i = 0; i < 8; i++) {
                    const u64 a2 = bcast2(w_s[cl * 129 + rg * 8 + i]);
                    #pragma unroll
                    for (int p = 0; p < 4; p++) ffma2(acc[i][p], a2, bfrag[p]);
                }
            }
        }
        __syncthreads();
        #pragma unroll
        for (int i = 0; i < 8; i++) {
            u64* zp = (u64*)(ze_s + (rg * 8 + i) * 128 + jg * 8);
            #pragma unroll
            for (int p = 0; p < 4; p++) zp[p] = acc[i][p];
        }
    }
    __syncthreads();

    // ---------------- column norms
    if (tid < TN) {
        float s = 0.0f;
        #pragma unroll 8
        for (int d = 0; d < DD; d++) {
            const float v = ze_s[d * 128 + tid];
            s = fmaf(v, v, s);
        }
        zsq_s[tid]  = s;
        zsrt_s[tid] = sqrtf(s);
    }
    __syncthreads();

    // ---------------- Phase 2: dots[k][j] + fused scaled-L2 argmin
    float zsq[8], zsr[8];
    #pragma unroll
    for (int jj = 0; jj < 8; jj++) {
        zsq[jj] = zsq_s[jg * 8 + jj];
        zsr[jj] = zsrt_s[jg * 8 + jj];
    }
    const float FINF = __int_as_float(0x7f800000);
    float bd[8], bn2[8]; int bk[8];
    #pragma unroll
    for (int jj = 0; jj < 8; jj++) { bd[jj] = FINF; bn2[jj] = 1.0f; bk[jj] = 0; }

    float* emb_s = buf;   // [KB][129]

    for (int kc = 0; kc < KK; kc += KB) {
        __syncthreads();
        #pragma unroll
        for (int it = 0; it < (KB * DD) / NTH; it++) {   // 32
            const int i = tid + it * NTH;
            const int kk = i >> 7, d = i & 127;
            emb_s[kk * 129 + d] = emb[(kc + kk) * DD + d];
        }
        if (tid < KB) { qsq_s[tid] = g_qsq[kc + tid]; qsrt_s[tid] = g_qsrt[kc + tid]; }
        __syncthreads();

        u64 dacc[4][4];
        #pragma unroll
        for (int i = 0; i < 4; i++)
            #pragma unroll
            for (int p = 0; p < 4; p++) dacc[i][p] = 0ull;

        #pragma unroll 2
        for (int d = 0; d < DD; d++) {
            u64 bfrag[4];
            const u64* bp = (const u64*)(ze_s + d * 128 + jg * 8);
            #pragma unroll
            for (int p = 0; p < 4; p++) bfrag[p] = bp[p];
            #pragma unroll
            for (int i = 0; i < 4; i++) {
                const u64 a2 = bcast2(emb_s[(rg * 4 + i) * 129 + d]);
                #pragma unroll
                for (int p = 0; p < 4; p++) ffma2(dacc[i][p], a2, bfrag[p]);
            }
        }

        // snorm^2 = dist / den^2 ; compare via cross-multiplication (no div):
        // cand better iff dist*bn2 < bd*n2 ; strict '<' keeps earliest k.
        #pragma unroll
        for (int i = 0; i < 4; i++) {
            const int   k  = kc + rg * 4 + i;
            const float qs = qsq_s[rg * 4 + i];
            const float qr = qsrt_s[rg * 4 + i];
            #pragma unroll
            for (int p = 0; p < 4; p++) {
                const u64 v = dacc[i][p];
                const float dlo = __uint_as_float((unsigned)v);
                const float dhi = __uint_as_float((unsigned)(v >> 32));
                {
                    const int jj = 2 * p;
                    const float dist = fmaxf(fmaf(-2.0f, dlo, zsq[jj] + qs), 0.0f);
                    const float den  = zsr[jj] + qr;
                    const float n2   = den * den;
                    if (dist * bn2[jj] < bd[jj] * n2) { bd[jj] = dist; bn2[jj] = n2; bk[jj] = k; }
                }
                {
                    const int jj = 2 * p + 1;
                    const float dist = fmaxf(fmaf(-2.0f, dhi, zsq[jj] + qs), 0.0f);
                    const float den  = zsr[jj] + qr;
                    const float n2   = den * den;
                    if (dist * bn2[jj] < bd[jj] * n2) { bd[jj] = dist; bn2[jj] = n2; bk[jj] = k; }
                }
            }
        }
    }

    // ---------------- cross-thread argmin reduction (16 k-groups per column)
    __syncthreads();
    float* redd = buf;                 // [16][128]
    float* redn = buf + 2048;          // [16][128]
    int*   redk = (int*)(buf + 4096);  // [16][128]
    #pragma unroll
    for (int jj = 0; jj < 8; jj++) {
        const int j = jg * 8 + jj;
        redd[rg * 128 + j] = bd[jj];
        redn[rg * 128 + j] = bn2[jj];
        redk[rg * 128 + j] = bk[jj];
    }
    __syncthreads();
    if (tid < TN) {
        const int j = tid;
        float cbd = redd[j], cbn = redn[j]; int cbk = redk[j];
        #pragma unroll
        for (int t = 1; t < 16; t++) {
            const float dd = redd[t * 128 + j];
            const float nn = redn[t * 128 + j];
            const int   kk = redk[t * 128 + j];
            const float l = dd * cbn, r = cbd * nn;
            if (l < r || (l == r && kk < cbk)) { cbd = dd; cbn = nn; cbk = kk; }
        }
        bestk_s[j] = cbk;
        atomicAdd(&g_nsum[cbk], 1.0f);   // exact integer adds -> deterministic
    }
    __syncthreads();

    // ---------------- epilogue: zq gather-out + EMA numerator scatter-add
    float* outz = out + ((size_t)b * DD) * NNN + n0;
    for (int idx = tid; idx < DD * TN; idx += NTH) {
        const int d = idx >> 7;       // slow: d
        const int j = idx & 127;      // fast: j  -> coalesced STG, conflict-free LDS
        const int k = bestk_s[j];
        outz[(size_t)d * NNN + j] = emb[k * DD + d];      // L2-resident gather
        atomicAdd(&g_zsum[k * DD + d], ze_s[d * 128 + j]);
    }
}

// ============================================================
// Kernel 3: EMA blend into d_out
// ============================================================
__global__ void vq_finalize(const float* __restrict__ ema_numer,
                            const float* __restrict__ ema_denom,
                            float* __restrict__ out)
{
    const int i = blockIdx.x * blockDim.x + threadIdx.x;
    if (i < KK * DD)
        out[ZQ_SIZE + i] = 0.99f * ema_numer[i] + 0.01f * g_zsum[i];
    if (i < KK)
        out[ZQ_SIZE + KK * DD + i] = 0.99f * ema_denom[i] + 0.01f * g_nsum[i];
}

// ============================================================
extern "C" void kernel_launch(void* const* d_in, const int* in_sizes, int n_in,
                              void* d_out, int out_size)
{
    const float* z         = (const float*)d_in[0];  // (B, N_IN, N)
    const float* W         = (const float*)d_in[1];  // (D, N_IN)
    const float* emb       = (const float*)d_in[2];  // (K, D)
    const float* ema_numer = (const float*)d_in[3];  // (K, D)
    const float* ema_denom = (const float*)d_in[4];  // (K,)
    float* out = (float*)d_out;

    const int smem_bytes = (DD * TN + 8256) * (int)sizeof(float);  // 98560 B
    cudaFuncSetAttribute(vq_main, cudaFuncAttributeMaxDynamicSharedMemorySize,
                         smem_bytes);

    vq_init<<<KK, 128>>>(emb);
    vq_main<<<BB * (NNN / TN), NTH, smem_bytes>>>(z, W, emb, out);
    vq_finalize<<<(KK * DD + 255) / 256, 256>>>(ema_numer, ema_denom, out);
}

// round 13
// speedup vs baseline: 1.0036x; 1.0036x over previous
#include <cuda_runtime.h>
#include <math.h>

// Problem constants
#define BB   8
#define NIN  256
#define DD   128
#define KK   1024
#define NNN  4096
#define TN   128          // columns per CTA tile
#define NTH  256          // threads per CTA
#define KB   64           // codebook rows per chunk
#define CB   32           // input channels per chunk (GEMM1)
#define ZQ_SIZE (BB*DD*NNN)

typedef unsigned long long u64;

// Scratch (no cudaMalloc allowed)
__device__ float g_zsum[KK*DD];
__device__ float g_nsum[KK];
__device__ float g_qsq[KK];
__device__ float g_qsrt[KK];

// ---- packed f32x2 helpers (FFMA2: 2x fp32 FMA throughput on sm_103a) ----
__device__ __forceinline__ u64 bcast2(float a) {
    u64 r; unsigned u = __float_as_uint(a);
    asm("mov.b64 %0, {%1, %1};" : "=l"(r) : "r"(u));
    return r;
}
__device__ __forceinline__ void ffma2(u64 &d, u64 a, u64 b) {
    asm("fma.rn.f32x2 %0, %1, %2, %0;" : "+l"(d) : "l"(a), "l"(b));
}

// ============================================================
// Kernel 1: zero scatter accumulators, precompute ||emb_k||^2 and sqrt
// grid = KK blocks of 128 threads (one block per codebook row)
// ============================================================
__global__ void vq_init(const float* __restrict__ emb) {
    const int k = blockIdx.x;
    const int t = threadIdx.x;
    const float v = emb[k * DD + t];
    g_zsum[k * DD + t] = 0.0f;
    float s = v * v;
    #pragma unroll
    for (int o = 16; o > 0; o >>= 1) s += __shfl_xor_sync(0xffffffffu, s, o);
    __shared__ float red[4];
    if ((t & 31) == 0) red[t >> 5] = s;
    __syncthreads();
    if (t == 0) {
        const float tot = (red[0] + red[1]) + (red[2] + red[3]);
        g_nsum[k] = 0.0f;
        g_qsq[k]  = tot;
        g_qsrt[k] = sqrtf(tot);
    }
}

// ============================================================
// Kernel 2: fused  ze-GEMM -> distance GEMM -> argmin -> zq gather
//           -> EMA scatter-add.   grid = BB * (NNN/TN) = 256 CTAs.
// ============================================================
__global__ void __launch_bounds__(NTH)
vq_main(const float* __restrict__ z, const float* __restrict__ W,
        const float* __restrict__ emb, float* __restrict__ out)
{
    extern __shared__ float smem[];
    float* ze_s = smem;            // [128 d][128 j]  = 16384 floats (64KB)
    float* buf  = smem + DD * TN;  // 8256-float union region (33KB)

    __shared__ float zsq_s[TN];
    __shared__ float zsrt_s[TN];
    __shared__ float qsq_s[KB];
    __shared__ float qsrt_s[KB];
    __shared__ int   bestk_s[TN];

    const int tid = threadIdx.x;
    const int b   = blockIdx.x >> 5;          // batch
    const int n0  = (blockIdx.x & 31) * TN;   // column tile origin
    const int rg  = tid & 15;                 // row group (d or k)
    const int jg  = tid >> 4;                 // column group (8 cols each)

    // ---------------- Phase 1: ze[d][j] = sum_c W[d][c] * z[b][c][n0+j]
    // register tile: 8 d-rows x 8 j-cols (4 f32x2 pairs) per thread
    {
        float* w_s  = buf;          // [CB][129]  (pad to kill write conflicts)
        float* zc_s = buf + 4160;   // [CB][128]
        u64 acc[8][4];
        #pragma unroll
        for (int i = 0; i < 8; i++)
            #pragma unroll
            for (int p = 0; p < 4; p++) acc[i][p] = 0ull;

        for (int cc = 0; cc < NIN; cc += CB) {
            __syncthreads();
            #pragma unroll
            for (int it = 0; it < (DD * CB) / NTH; it++) {     // 16
                const int i = tid + it * NTH;
                const int d = i >> 5, cl = i & 31;
                w_s[cl * 129 + d] = W[d * NIN + cc + cl];
            }
            #pragma unroll
            for (int it = 0; it < (CB * TN) / NTH; it++) {     // 16
                const int i = tid + it * NTH;
                const int cl = i >> 7, j = i & 127;
                zc_s[cl * 128 + j] = z[((size_t)b * NIN + cc + cl) * NNN + n0 + j];
            }
            __syncthreads();
            #pragma unroll 2
            for (int cl = 0; cl < CB; cl++) {
                u64 bfrag[4];
                const u64* bp = (const u64*)(zc_s + cl * 128 + jg * 8);
                #pragma unroll
                for (int p = 0; p < 4; p++) bfrag[p] = bp[p];
                #pragma unroll
                for (int i = 0; i < 8; i++) {
                    const u64 a2 = bcast2(w_s[cl * 129 + rg * 8 + i]);
                    #pragma unroll
                    for (int p = 0; p < 4; p++) ffma2(acc[i][p], a2, bfrag[p]);
                }
            }
        }
        __syncthreads();
        #pragma unroll
        for (int i = 0; i < 8; i++) {
            u64* zp = (u64*)(ze_s + (rg * 8 + i) * 128 + jg * 8);
            #pragma unroll
            for (int p = 0; p < 4; p++) zp[p] = acc[i][p];
        }
    }
    __syncthreads();

    // ---------------- column norms
    if (tid < TN) {
        float s = 0.0f;
        #pragma unroll 8
        for (int d = 0; d < DD; d++) {
            const float v = ze_s[d * 128 + tid];
            s = fmaf(v, v, s);
        }
        zsq_s[tid]  = s;
        zsrt_s[tid] = sqrtf(s);
    }
    __syncthreads();

    // ---------------- Phase 2: dots[k][j] + fused scaled-L2 argmin
    float zsq[8], zsr[8];
    #pragma unroll
    for (int jj = 0; jj < 8; jj++) {
        zsq[jj] = zsq_s[jg * 8 + jj];
        zsr[jj] = zsrt_s[jg * 8 + jj];
    }
    const float FINF = __int_as_float(0x7f800000);
    float bd[8], bn2[8]; int bk[8];
    #pragma unroll
    for (int jj = 0; jj < 8; jj++) { bd[jj] = FINF; bn2[jj] = 1.0f; bk[jj] = 0; }

    float* emb_s = buf;   // [KB][129]

    for (int kc = 0; kc < KK; kc += KB) {
        __syncthreads();
        #pragma unroll
        for (int it = 0; it < (KB * DD) / NTH; it++) {   // 32
            const int i = tid + it * NTH;
            const int kk = i >> 7, d = i & 127;
            emb_s[kk * 129 + d] = emb[(kc + kk) * DD + d];
        }
        if (tid < KB) { qsq_s[tid] = g_qsq[kc + tid]; qsrt_s[tid] = g_qsrt[kc + tid]; }
        __syncthreads();

        u64 dacc[4][4];
        #pragma unroll
        for (int i = 0; i < 4; i++)
            #pragma unroll
            for (int p = 0; p < 4; p++) dacc[i][p] = 0ull;

        #pragma unroll 2
        for (int d = 0; d < DD; d++) {
            u64 bfrag[4];
            const u64* bp = (const u64*)(ze_s + d * 128 + jg * 8);
            #pragma unroll
            for (int p = 0; p < 4; p++) bfrag[p] = bp[p];
            #pragma unroll
            for (int i = 0; i < 4; i++) {
                const u64 a2 = bcast2(emb_s[(rg * 4 + i) * 129 + d]);
                #pragma unroll
                for (int p = 0; p < 4; p++) ffma2(dacc[i][p], a2, bfrag[p]);
            }
        }

        // snorm^2 = dist / den^2 ; compare via cross-multiplication (no div):
        // cand better iff dist*bn2 < bd*n2 ; strict '<' keeps earliest k.
        #pragma unroll
        for (int i = 0; i < 4; i++) {
            const int   k  = kc + rg * 4 + i;
            const float qs = qsq_s[rg * 4 + i];
            const float qr = qsrt_s[rg * 4 + i];
            #pragma unroll
            for (int p = 0; p < 4; p++) {
                const u64 v = dacc[i][p];
                const float dlo = __uint_as_float((unsigned)v);
                const float dhi = __uint_as_float((unsigned)(v >> 32));
                {
                    const int jj = 2 * p;
                    const float dist = fmaxf(fmaf(-2.0f, dlo, zsq[jj] + qs), 0.0f);
                    const float den  = zsr[jj] + qr;
                    const float n2   = den * den;
                    if (dist * bn2[jj] < bd[jj] * n2) { bd[jj] = dist; bn2[jj] = n2; bk[jj] = k; }
                }
                {
                    const int jj = 2 * p + 1;
                    const float dist = fmaxf(fmaf(-2.0f, dhi, zsq[jj] + qs), 0.0f);
                    const float den  = zsr[jj] + qr;
                    const float n2   = den * den;
                    if (dist * bn2[jj] < bd[jj] * n2) { bd[jj] = dist; bn2[jj] = n2; bk[jj] = k; }
                }
            }
        }
    }

    // ---------------- cross-thread argmin reduction (16 k-groups per column)
    __syncthreads();
    float* redd = buf;                 // [16][128]
    float* redn = buf + 2048;          // [16][128]
    int*   redk = (int*)(buf + 4096);  // [16][128]
    #pragma unroll
    for (int jj = 0; jj < 8; jj++) {
        const int j = jg * 8 + jj;
        redd[rg * 128 + j] = bd[jj];
        redn[rg * 128 + j] = bn2[jj];
        redk[rg * 128 + j] = bk[jj];
    }
    __syncthreads();
    if (tid < TN) {
        const int j = tid;
        float cbd = redd[j], cbn = redn[j]; int cbk = redk[j];
        #pragma unroll
        for (int t = 1; t < 16; t++) {
            const float dd = redd[t * 128 + j];
            const float nn = redn[t * 128 + j];
            const int   kk = redk[t * 128 + j];
            const float l = dd * cbn, r = cbd * nn;
            if (l < r || (l == r && kk < cbk)) { cbd = dd; cbn = nn; cbk = kk; }
        }
        bestk_s[j] = cbk;
        atomicAdd(&g_nsum[cbk], 1.0f);   // exact integer adds -> deterministic
    }
    __syncthreads();

    // ---------------- epilogue: zq gather-out + EMA numerator scatter-add
    float* outz = out + ((size_t)b * DD) * NNN + n0;
    for (int idx = tid; idx < DD * TN; idx += NTH) {
        const int d = idx >> 7;       // slow: d
        const int j = idx & 127;      // fast: j  -> coalesced STG, conflict-free LDS
        const int k = bestk_s[j];
        outz[(size_t)d * NNN + j] = emb[k * DD + d];      // L2-resident gather
        atomicAdd(&g_zsum[k * DD + d], ze_s[d * 128 + j]);
    }
}

// ============================================================
// Kernel 3: EMA blend into d_out
// ============================================================
__global__ void vq_finalize(const float* __restrict__ ema_numer,
                            const float* __restrict__ ema_denom,
                            float* __restrict__ out)
{
    const int i = blockIdx.x * blockDim.x + threadIdx.x;
    if (i < KK * DD)
        out[ZQ_SIZE + i] = 0.99f * ema_numer[i] + 0.01f * g_zsum[i];
    if (i < KK)
        out[ZQ_SIZE + KK * DD + i] = 0.99f * ema_denom[i] + 0.01f * g_nsum[i];
}

// ============================================================
extern "C" void kernel_launch(void* const* d_in, const int* in_sizes, int n_in,
                              void* d_out, int out_size)
{
    const float* z         = (const float*)d_in[0];  // (B, N_IN, N)
    const float* W         = (const float*)d_in[1];  // (D, N_IN)
    const float* emb       = (const float*)d_in[2];  // (K, D)
    const float* ema_numer = (const float*)d_in[3];  // (K, D)
    const float* ema_denom = (const float*)d_in[4];  // (K,)
    float* out = (float*)d_out;

    const int smem_bytes = (DD * TN + 8256) * (int)sizeof(float);  // 98560 B
    cudaFuncSetAttribute(vq_main, cudaFuncAttributeMaxDynamicSharedMemorySize,
                         smem_bytes);

    vq_init<<<KK, 128>>>(emb);
    vq_main<<<BB * (NNN / TN), NTH, smem_bytes>>>(z, W, emb, out);
    vq_finalize<<<(KK * DD + 255) / 256, 256>>>(ema_numer, ema_denom, out);
}

// round 14
// speedup vs baseline: 1.0046x; 1.0010x over previous
#include <cuda_runtime.h>
#include <math.h>

// Problem constants
#define BB   8
#define NIN  256
#define DD   128
#define KK   1024
#define NNN  4096
#define TN   128          // columns per CTA tile
#define NTH  256          // threads per CTA
#define KB   64           // codebook rows per chunk
#define CB   32           // input channels per chunk (GEMM1)
#define ZQ_SIZE (BB*DD*NNN)

typedef unsigned long long u64;

// Scratch (no cudaMalloc allowed)
__device__ float g_zsum[KK*DD];
__device__ float g_nsum[KK];
__device__ float g_qsq[KK];
__device__ float g_qsrt[KK];

// ---- packed f32x2 helpers (FFMA2: 2x fp32 FMA throughput on sm_103a) ----
__device__ __forceinline__ u64 bcast2(float a) {
    u64 r; unsigned u = __float_as_uint(a);
    asm("mov.b64 %0, {%1, %1};" : "=l"(r) : "r"(u));
    return r;
}
__device__ __forceinline__ void ffma2(u64 &d, u64 a, u64 b) {
    asm("fma.rn.f32x2 %0, %1, %2, %0;" : "+l"(d) : "l"(a), "l"(b));
}

// ============================================================
// Kernel 1: zero scatter accumulators, precompute ||emb_k||^2 and sqrt
// grid = KK blocks of 128 threads (one block per codebook row)
// ============================================================
__global__ void vq_init(const float* __restrict__ emb) {
    const int k = blockIdx.x;
    const int t = threadIdx.x;
    const float v = emb[k * DD + t];
    g_zsum[k * DD + t] = 0.0f;
    float s = v * v;
    #pragma unroll
    for (int o = 16; o > 0; o >>= 1) s += __shfl_xor_sync(0xffffffffu, s, o);
    __shared__ float red[4];
    if ((t & 31) == 0) red[t >> 5] = s;
    __syncthreads();
    if (t == 0) {
        const float tot = (red[0] + red[1]) + (red[2] + red[3]);
        g_nsum[k] = 0.0f;
        g_qsq[k]  = tot;
        g_qsrt[k] = sqrtf(tot);
    }
}

// ============================================================
// Kernel 2: fused  ze-GEMM -> distance GEMM -> argmin -> zq gather
//           -> EMA scatter-add.   grid = BB * (NNN/TN) = 256 CTAs.
// ============================================================
__global__ void __launch_bounds__(NTH)
vq_main(const float* __restrict__ z, const float* __restrict__ W,
        const float* __restrict__ emb, float* __restrict__ out)
{
    extern __shared__ float smem[];
    float* ze_s = smem;            // [128 d][128 j]  = 16384 floats (64KB)
    float* buf  = smem + DD * TN;  // 8256-float union region (33KB)

    __shared__ float zsq_s[TN];
    __shared__ float zsrt_s[TN];
    __shared__ float qsq_s[KB];
    __shared__ float qsrt_s[KB];
    __shared__ int   bestk_s[TN];

    const int tid = threadIdx.x;
    const int b   = blockIdx.x >> 5;          // batch
    const int n0  = (blockIdx.x & 31) * TN;   // column tile origin
    const int rg  = tid & 15;                 // row group (d or k)
    const int jg  = tid >> 4;                 // column group (8 cols each)

    // ---------------- Phase 1: ze[d][j] = sum_c W[d][c] * z[b][c][n0+j]
    // register tile: 8 d-rows x 8 j-cols (4 f32x2 pairs) per thread
    {
        float* w_s  = buf;          // [CB][129]  (pad to kill write conflicts)
        float* zc_s = buf + 4160;   // [CB][128]
        u64 acc[8][4];
        #pragma unroll
        for (int i = 0; i < 8; i++)
            #pragma unroll
            for (int p = 0; p < 4; p++) acc[i][p] = 0ull;

        for (int cc = 0; cc < NIN; cc += CB) {
            __syncthreads();
            #pragma unroll
            for (int it = 0; it < (DD * CB) / NTH; it++) {     // 16
                const int i = tid + it * NTH;
                const int d = i >> 5, cl = i & 31;
                w_s[cl * 129 + d] = W[d * NIN + cc + cl];
            }
            #pragma unroll
            for (int it = 0; it < (CB * TN) / NTH; it++) {     // 16
                const int i = tid + it * NTH;
                const int cl = i >> 7, j = i & 127;
                zc_s[cl * 128 + j] = z[((size_t)b * NIN + cc + cl) * NNN + n0 + j];
            }
            __syncthreads();
            #pragma unroll 2
            for (int cl = 0; cl < CB; cl++) {
                u64 bfrag[4];
                const u64* bp = (const u64*)(zc_s + cl * 128 + jg * 8);
                #pragma unroll
                for (int p = 0; p < 4; p++) bfrag[p] = bp[p];
                #pragma unroll
                for (int i = 0; i < 8; i++) {
                    const u64 a2 = bcast2(w_s[cl * 129 + rg * 8 + i]);
                    #pragma unroll
                    for (int p = 0; p < 4; p++) ffma2(acc[i][p], a2, bfrag[p]);
                }
            }
        }
        __syncthreads();
        #pragma unroll
        for (int i = 0; i < 8; i++) {
            u64* zp = (u64*)(ze_s + (rg * 8 + i) * 128 + jg * 8);
            #pragma unroll
            for (int p = 0; p < 4; p++) zp[p] = acc[i][p];
        }
    }
    __syncthreads();

    // ---------------- column norms
    if (tid < TN) {
        float s = 0.0f;
        #pragma unroll 8
        for (int d = 0; d < DD; d++) {
            const float v = ze_s[d * 128 + tid];
            s = fmaf(v, v, s);
        }
        zsq_s[tid]  = s;
        zsrt_s[tid] = sqrtf(s);
    }
    __syncthreads();

    // ---------------- Phase 2: dots[k][j] + fused scaled-L2 argmin
    float zsq[8], zsr[8];
    #pragma unroll
    for (int jj = 0; jj < 8; jj++) {
        zsq[jj] = zsq_s[jg * 8 + jj];
        zsr[jj] = zsrt_s[jg * 8 + jj];
    }
    const float FINF = __int_as_float(0x7f800000);
    float bd[8], bn2[8]; int bk[8];
    #pragma unroll
    for (int jj = 0; jj < 8; jj++) { bd[jj] = FINF; bn2[jj] = 1.0f; bk[jj] = 0; }

    float* emb_s = buf;   // [KB][129]

    for (int kc = 0; kc < KK; kc += KB) {
        __syncthreads();
        #pragma unroll
        for (int it = 0; it < (KB * DD) / NTH; it++) {   // 32
            const int i = tid + it * NTH;
            const int kk = i >> 7, d = i & 127;
            emb_s[kk * 129 + d] = emb[(kc + kk) * DD + d];
        }
        if (tid < KB) { qsq_s[tid] = g_qsq[kc + tid]; qsrt_s[tid] = g_qsrt[kc + tid]; }
        __syncthreads();

        u64 dacc[4][4];
        #pragma unroll
        for (int i = 0; i < 4; i++)
            #pragma unroll
            for (int p = 0; p < 4; p++) dacc[i][p] = 0ull;

        #pragma unroll 2
        for (int d = 0; d < DD; d++) {
            u64 bfrag[4];
            const u64* bp = (const u64*)(ze_s + d * 128 + jg * 8);
            #pragma unroll
            for (int p = 0; p < 4; p++) bfrag[p] = bp[p];
            #pragma unroll
            for (int i = 0; i < 4; i++) {
                const u64 a2 = bcast2(emb_s[(rg * 4 + i) * 129 + d]);
                #pragma unroll
                for (int p = 0; p < 4; p++) ffma2(dacc[i][p], a2, bfrag[p]);
            }
        }

        // snorm^2 = dist / den^2 ; compare via cross-multiplication (no div):
        // cand better iff dist*bn2 < bd*n2 ; strict '<' keeps earliest k.
        #pragma unroll
        for (int i = 0; i < 4; i++) {
            const int   k  = kc + rg * 4 + i;
            const float qs = qsq_s[rg * 4 + i];
            const float qr = qsrt_s[rg * 4 + i];
            #pragma unroll
            for (int p = 0; p < 4; p++) {
                const u64 v = dacc[i][p];
                const float dlo = __uint_as_float((unsigned)v);
                const float dhi = __uint_as_float((unsigned)(v >> 32));
                {
                    const int jj = 2 * p;
                    const float dist = fmaxf(fmaf(-2.0f, dlo, zsq[jj] + qs), 0.0f);
                    const float den  = zsr[jj] + qr;
                    const float n2   = den * den;
                    if (dist * bn2[jj] < bd[jj] * n2) { bd[jj] = dist; bn2[jj] = n2; bk[jj] = k; }
                }
                {
                    const int jj = 2 * p + 1;
                    const float dist = fmaxf(fmaf(-2.0f, dhi, zsq[jj] + qs), 0.0f);
                    const float den  = zsr[jj] + qr;
                    const float n2   = den * den;
                    if (dist * bn2[jj] < bd[jj] * n2) { bd[jj] = dist; bn2[jj] = n2; bk[jj] = k; }
                }
            }
        }
    }

    // ---------------- cross-thread argmin reduction (16 k-groups per column)
    __syncthreads();
    float* redd = buf;                 // [16][128]
    float* redn = buf + 2048;          // [16][128]
    int*   redk = (int*)(buf + 4096);  // [16][128]
    #pragma unroll
    for (int jj = 0; jj < 8; jj++) {
        const int j = jg * 8 + jj;
        redd[rg * 128 + j] = bd[jj];
        redn[rg * 128 + j] = bn2[jj];
        redk[rg * 128 + j] = bk[jj];
    }
    __syncthreads();
    if (tid < TN) {
        const int j = tid;
        float cbd = redd[j], cbn = redn[j]; int cbk = redk[j];
        #pragma unroll
        for (int t = 1; t < 16; t++) {
            const float dd = redd[t * 128 + j];
            const float nn = redn[t * 128 + j];
            const int   kk = redk[t * 128 + j];
            const float l = dd * cbn, r = cbd * nn;
            if (l < r || (l == r && kk < cbk)) { cbd = dd; cbn = nn; cbk = kk; }
        }
        bestk_s[j] = cbk;
        atomicAdd(&g_nsum[cbk], 1.0f);   // exact integer adds -> deterministic
    }
    __syncthreads();

    // ---------------- epilogue: zq gather-out + EMA numerator scatter-add
    float* outz = out + ((size_t)b * DD) * NNN + n0;
    for (int idx = tid; idx < DD * TN; idx += NTH) {
        const int d = idx >> 7;       // slow: d
        const int j = idx & 127;      // fast: j  -> coalesced STG, conflict-free LDS
        const int k = bestk_s[j];
        outz[(size_t)d * NNN + j] = emb[k * DD + d];      // L2-resident gather
        atomicAdd(&g_zsum[k * DD + d], ze_s[d * 128 + j]);
    }
}

// ============================================================
// Kernel 3: EMA blend into d_out
// ============================================================
__global__ void vq_finalize(const float* __restrict__ ema_numer,
                            const float* __restrict__ ema_denom,
                            float* __restrict__ out)
{
    const int i = blockIdx.x * blockDim.x + threadIdx.x;
    if (i < KK * DD)
        out[ZQ_SIZE + i] = 0.99f * ema_numer[i] + 0.01f * g_zsum[i];
    if (i < KK)
        out[ZQ_SIZE + KK * DD + i] = 0.99f * ema_denom[i] + 0.01f * g_nsum[i];
}

// ============================================================
extern "C" void kernel_launch(void* const* d_in, const int* in_sizes, int n_in,
                              void* d_out, int out_size)
{
    const float* z         = (const float*)d_in[0];  // (B, N_IN, N)
    const float* W         = (const float*)d_in[1];  // (D, N_IN)
    const float* emb       = (const float*)d_in[2];  // (K, D)
    const float* ema_numer = (const float*)d_in[3];  // (K, D)
    const float* ema_denom = (const float*)d_in[4];  // (K,)
    float* out = (float*)d_out;

    const int smem_bytes = (DD * TN + 8256) * (int)sizeof(float);  // 98560 B
    cudaFuncSetAttribute(vq_main, cudaFuncAttributeMaxDynamicSharedMemorySize,
                         smem_bytes);

    vq_init<<<KK, 128>>>(emb);
    vq_main<<<BB * (NNN / TN), NTH, smem_bytes>>>(z, W, emb, out);
    vq_finalize<<<(KK * DD + 255) / 256, 256>>>(ema_numer, ema_denom, out);
}

// round 15
// speedup vs baseline: 1.0052x; 1.0005x over previous
#include <cuda_runtime.h>
#include <math.h>

// Problem constants
#define BB   8
#define NIN  256
#define DD   128
#define KK   1024
#define NNN  4096
#define TN   128          // columns per CTA tile
#define NTH  256          // threads per CTA
#define KB   64           // codebook rows per chunk
#define CB   32           // input channels per chunk (GEMM1)
#define ZQ_SIZE (BB*DD*NNN)

typedef unsigned long long u64;

// Scratch (no cudaMalloc allowed)
__device__ float g_zsum[KK*DD];
__device__ float g_nsum[KK];
__device__ float g_qsq[KK];
__device__ float g_qsrt[KK];

// ---- packed f32x2 helpers (FFMA2: 2x fp32 FMA throughput on sm_103a) ----
__device__ __forceinline__ u64 bcast2(float a) {
    u64 r; unsigned u = __float_as_uint(a);
    asm("mov.b64 %0, {%1, %1};" : "=l"(r) : "r"(u));
    return r;
}
__device__ __forceinline__ void ffma2(u64 &d, u64 a, u64 b) {
    asm("fma.rn.f32x2 %0, %1, %2, %0;" : "+l"(d) : "l"(a), "l"(b));
}

// ============================================================
// Kernel 1: zero scatter accumulators, precompute ||emb_k||^2 and sqrt
// grid = KK blocks of 128 threads (one block per codebook row)
// ============================================================
__global__ void vq_init(const float* __restrict__ emb) {
    const int k = blockIdx.x;
    const int t = threadIdx.x;
    const float v = emb[k * DD + t];
    g_zsum[k * DD + t] = 0.0f;
    float s = v * v;
    #pragma unroll
    for (int o = 16; o > 0; o >>= 1) s += __shfl_xor_sync(0xffffffffu, s, o);
    __shared__ float red[4];
    if ((t & 31) == 0) red[t >> 5] = s;
    __syncthreads();
    if (t == 0) {
        const float tot = (red[0] + red[1]) + (red[2] + red[3]);
        g_nsum[k] = 0.0f;
        g_qsq[k]  = tot;
        g_qsrt[k] = sqrtf(tot);
    }
}

// ============================================================
// Kernel 2: fused  ze-GEMM -> distance GEMM -> argmin -> zq gather
//           -> EMA scatter-add.   grid = BB * (NNN/TN) = 256 CTAs.
// ============================================================
__global__ void __launch_bounds__(NTH)
vq_main(const float* __restrict__ z, const float* __restrict__ W,
        const float* __restrict__ emb, float* __restrict__ out)
{
    extern __shared__ float smem[];
    float* ze_s = smem;            // [128 d][128 j]  = 16384 floats (64KB)
    float* buf  = smem + DD * TN;  // 8256-float union region (33KB)

    __shared__ float zsq_s[TN];
    __shared__ float zsrt_s[TN];
    __shared__ float qsq_s[KB];
    __shared__ float qsrt_s[KB];
    __shared__ int   bestk_s[TN];

    const int tid = threadIdx.x;
    const int b   = blockIdx.x >> 5;          // batch
    const int n0  = (blockIdx.x & 31) * TN;   // column tile origin
    const int rg  = tid & 15;                 // row group (d or k)
    const int jg  = tid >> 4;                 // column group (8 cols each)

    // ---------------- Phase 1: ze[d][j] = sum_c W[d][c] * z[b][c][n0+j]
    // register tile: 8 d-rows x 8 j-cols (4 f32x2 pairs) per thread
    {
        float* w_s  = buf;          // [CB][129]  (pad to kill write conflicts)
        float* zc_s = buf + 4160;   // [CB][128]
        u64 acc[8][4];
        #pragma unroll
        for (int i = 0; i < 8; i++)
            #pragma unroll
            for (int p = 0; p < 4; p++) acc[i][p] = 0ull;

        for (int cc = 0; cc < NIN; cc += CB) {
            __syncthreads();
            #pragma unroll
            for (int it = 0; it < (DD * CB) / NTH; it++) {     // 16
                const int i = tid + it * NTH;
                const int d = i >> 5, cl = i & 31;
                w_s[cl * 129 + d] = W[d * NIN + cc + cl];
            }
            #pragma unroll
            for (int it = 0; it < (CB * TN) / NTH; it++) {     // 16
                const int i = tid + it * NTH;
                const int cl = i >> 7, j = i & 127;
                zc_s[cl * 128 + j] = z[((size_t)b * NIN + cc + cl) * NNN + n0 + j];
            }
            __syncthreads();
            #pragma unroll 2
            for (int cl = 0; cl < CB; cl++) {
                u64 bfrag[4];
                const u64* bp = (const u64*)(zc_s + cl * 128 + jg * 8);
                #pragma unroll
                for (int p = 0; p < 4; p++) bfrag[p] = bp[p];
                #pragma unroll
                for (int i = 0; i < 8; i++) {
                    const u64 a2 = bcast2(w_s[cl * 129 + rg * 8 + i]);
                    #pragma unroll
                    for (int p = 0; p < 4; p++) ffma2(acc[i][p], a2, bfrag[p]);
                }
            }
        }
        __syncthreads();
        #pragma unroll
        for (int i = 0; i < 8; i++) {
            u64* zp = (u64*)(ze_s + (rg * 8 + i) * 128 + jg * 8);
            #pragma unroll
            for (int p = 0; p < 4; p++) zp[p] = acc[i][p];
        }
    }
    __syncthreads();

    // ---------------- column norms
    if (tid < TN) {
        float s = 0.0f;
        #pragma unroll 8
        for (int d = 0; d < DD; d++) {
            const float v = ze_s[d * 128 + tid];
            s = fmaf(v, v, s);
        }
        zsq_s[tid]  = s;
        zsrt_s[tid] = sqrtf(s);
    }
    __syncthreads();

    // ---------------- Phase 2: dots[k][j] + fused scaled-L2 argmin
    float zsq[8], zsr[8];
    #pragma unroll
    for (int jj = 0; jj < 8; jj++) {
        zsq[jj] = zsq_s[jg * 8 + jj];
        zsr[jj] = zsrt_s[jg * 8 + jj];
    }
    const float FINF = __int_as_float(0x7f800000);
    float bd[8], bn2[8]; int bk[8];
    #pragma unroll
    for (int jj = 0; jj < 8; jj++) { bd[jj] = FINF; bn2[jj] = 1.0f; bk[jj] = 0; }

    float* emb_s = buf;   // [KB][129]

    for (int kc = 0; kc < KK; kc += KB) {
        __syncthreads();
        #pragma unroll
        for (int it = 0; it < (KB * DD) / NTH; it++) {   // 32
            const int i = tid + it * NTH;
            const int kk = i >> 7, d = i & 127;
            emb_s[kk * 129 + d] = emb[(kc + kk) * DD + d];
        }
        if (tid < KB) { qsq_s[tid] = g_qsq[kc + tid]; qsrt_s[tid] = g_qsrt[kc + tid]; }
        __syncthreads();

        u64 dacc[4][4];
        #pragma unroll
        for (int i = 0; i < 4; i++)
            #pragma unroll
            for (int p = 0; p < 4; p++) dacc[i][p] = 0ull;

        #pragma unroll 2
        for (int d = 0; d < DD; d++) {
            u64 bfrag[4];
            const u64* bp = (const u64*)(ze_s + d * 128 + jg * 8);
            #pragma unroll
            for (int p = 0; p < 4; p++) bfrag[p] = bp[p];
            #pragma unroll
            for (int i = 0; i < 4; i++) {
                const u64 a2 = bcast2(emb_s[(rg * 4 + i) * 129 + d]);
                #pragma unroll
                for (int p = 0; p < 4; p++) ffma2(dacc[i][p], a2, bfrag[p]);
            }
        }

        // snorm^2 = dist / den^2 ; compare via cross-multiplication (no div):
        // cand better iff dist*bn2 < bd*n2 ; strict '<' keeps earliest k.
        #pragma unroll
        for (int i = 0; i < 4; i++) {
            const int   k  = kc + rg * 4 + i;
            const float qs = qsq_s[rg * 4 + i];
            const float qr = qsrt_s[rg * 4 + i];
            #pragma unroll
            for (int p = 0; p < 4; p++) {
                const u64 v = dacc[i][p];
                const float dlo = __uint_as_float((unsigned)v);
                const float dhi = __uint_as_float((unsigned)(v >> 32));
                {
                    const int jj = 2 * p;
                    const float dist = fmaxf(fmaf(-2.0f, dlo, zsq[jj] + qs), 0.0f);
                    const float den  = zsr[jj] + qr;
                    const float n2   = den * den;
                    if (dist * bn2[jj] < bd[jj] * n2) { bd[jj] = dist; bn2[jj] = n2; bk[jj] = k; }
                }
                {
                    const int jj = 2 * p + 1;
                    const float dist = fmaxf(fmaf(-2.0f, dhi, zsq[jj] + qs), 0.0f);
                    const float den  = zsr[jj] + qr;
                    const float n2   = den * den;
                    if (dist * bn2[jj] < bd[jj] * n2) { bd[jj] = dist; bn2[jj] = n2; bk[jj] = k; }
                }
            }
        }
    }

    // ---------------- cross-thread argmin reduction (16 k-groups per column)
    __syncthreads();
    float* redd = buf;                 // [16][128]
    float* redn = buf + 2048;          // [16][128]
    int*   redk = (int*)(buf + 4096);  // [16][128]
    #pragma unroll
    for (int jj = 0; jj < 8; jj++) {
        const int j = jg * 8 + jj;
        redd[rg * 128 + j] = bd[jj];
        redn[rg * 128 + j] = bn2[jj];
        redk[rg * 128 + j] = bk[jj];
    }
    __syncthreads();
    if (tid < TN) {
        const int j = tid;
        float cbd = redd[j], cbn = redn[j]; int cbk = redk[j];
        #pragma unroll
        for (int t = 1; t < 16; t++) {
            const float dd = redd[t * 128 + j];
            const float nn = redn[t * 128 + j];
            const int   kk = redk[t * 128 + j];
            const float l = dd * cbn, r = cbd * nn;
            if (l < r || (l == r && kk < cbk)) { cbd = dd; cbn = nn; cbk = kk; }
        }
        bestk_s[j] = cbk;
        atomicAdd(&g_nsum[cbk], 1.0f);   // exact integer adds -> deterministic
    }
    __syncthreads();

    // ---------------- epilogue: zq gather-out + EMA numerator scatter-add
    float* outz = out + ((size_t)b * DD) * NNN + n0;
    for (int idx = tid; idx < DD * TN; idx += NTH) {
        const int d = idx >> 7;       // slow: d
        const int j = idx & 127;      // fast: j  -> coalesced STG, conflict-free LDS
        const int k = bestk_s[j];
        outz[(size_t)d * NNN + j] = emb[k * DD + d];      // L2-resident gather
        atomicAdd(&g_zsum[k * DD + d], ze_s[d * 128 + j]);
    }
}

// ============================================================
// Kernel 3: EMA blend into d_out
// ============================================================
__global__ void vq_finalize(const float* __restrict__ ema_numer,
                            const float* __restrict__ ema_denom,
                            float* __restrict__ out)
{
    const int i = blockIdx.x * blockDim.x + threadIdx.x;
    if (i < KK * DD)
        out[ZQ_SIZE + i] = 0.99f * ema_numer[i] + 0.01f * g_zsum[i];
    if (i < KK)
        out[ZQ_SIZE + KK * DD + i] = 0.99f * ema_denom[i] + 0.01f * g_nsum[i];
}

// ============================================================
extern "C" void kernel_launch(void* const* d_in, const int* in_sizes, int n_in,
                              void* d_out, int out_size)
{
    const float* z         = (const float*)d_in[0];  // (B, N_IN, N)
    const float* W         = (const float*)d_in[1];  // (D, N_IN)
    const float* emb       = (const float*)d_in[2];  // (K, D)
    const float* ema_numer = (const float*)d_in[3];  // (K, D)
    const float* ema_denom = (const float*)d_in[4];  // (K,)
    float* out = (float*)d_out;

    const int smem_bytes = (DD * TN + 8256) * (int)sizeof(float);  // 98560 B
    cudaFuncSetAttribute(vq_main, cudaFuncAttributeMaxDynamicSharedMemorySize,
                         smem_bytes);

    vq_init<<<KK, 128>>>(emb);
    vq_main<<<BB * (NNN / TN), NTH, smem_bytes>>>(z, W, emb, out);
    vq_finalize<<<(KK * DD + 255) / 256, 256>>>(ema_numer, ema_denom, out);
}